// round 17
// baseline (speedup 1.0000x reference)
#include <cuda_runtime.h>

// Shape fixed by the reference: B=1, T=2,000,000, C=16 -> 32M floats.
#define NCOL 16
#define NB   1184    // reduce grid: 8 waves of 148 SMs
#define NT   256
#define NB2  592     // fix grid

// Graph-replay-safe scratch: __device__ globals (no allocation allowed).
__device__ float        g_sum[NCOL];
__device__ unsigned int g_cnt[NCOL];
// NaN bitmask: one bit per element, 32M elems -> 1M words (4 MB).
// Layout: group g covers float4 indices [32g, 32g+32) = elements [128g, 128g+128).
//   word[4g+k] bit l  <->  element 128g + 4l + k   (k = component 0..3, l = lane)
// Fully overwritten by pass 1 every replay -> no init needed.
#define MASK_WORDS 1048576
__device__ unsigned int g_mask[MASK_WORDS];

// ---------------------------------------------------------------------------
// 1) Zero the accumulators (must run on every graph replay).
// ---------------------------------------------------------------------------
__global__ void k_init() {
    int i = threadIdx.x;
    if (i < NCOL) {
        g_sum[i] = 0.0f;
        g_cnt[i] = 0u;
    }
}

// ---------------------------------------------------------------------------
// 2) Fused: per-column sum/count reduce + raw copy to out + NaN bitmask emit.
//    Grid-stride over float4; stride % 32 == 0, so a warp's 32 lanes always
//    cover one aligned 32-float4 group, and each thread's float4 stays on a
//    fixed 4-column group (cols [(p&3)*4 .. +3]).
// ---------------------------------------------------------------------------
struct Acc {
    float    s0 = 0.f, s1 = 0.f, s2 = 0.f, s3 = 0.f;
    unsigned c0 = 0u,  c1 = 0u,  c2 = 0u,  c3 = 0u;
};

__device__ __forceinline__ void process(const float4* __restrict__ in4,
                                        float4* __restrict__ out4,
                                        int p, int lane, Acc& a) {
    float4 v = __ldcs(&in4[p]);
    bool n0 = !(v.x == v.x), n1 = !(v.y == v.y), n2 = !(v.z == v.z), n3 = !(v.w == v.w);
    a.s0 += n0 ? 0.0f : v.x;  a.c0 += !n0;
    a.s1 += n1 ? 0.0f : v.y;  a.c1 += !n1;
    a.s2 += n2 ? 0.0f : v.z;  a.c2 += !n2;
    a.s3 += n3 ? 0.0f : v.w;  a.c3 += !n3;
    __stcs(&out4[p], v);                       // raw copy; NaNs patched in pass 2
    unsigned b0 = __ballot_sync(0xffffffffu, n0);
    unsigned b1 = __ballot_sync(0xffffffffu, n1);
    unsigned b2 = __ballot_sync(0xffffffffu, n2);
    unsigned b3 = __ballot_sync(0xffffffffu, n3);
    if (lane == 0) {                           // p is 32-aligned in lane 0
        uint4* dst = reinterpret_cast<uint4*>(&g_mask[(unsigned)p >> 3]); // 4*(p/32)
        __stcs(dst, make_uint4(b0, b1, b2, b3));
    }
}

__global__ void __launch_bounds__(NT) k_reduce_copy(const float4* __restrict__ in4,
                                                    float4* __restrict__ out4, int n4) {
    __shared__ float        ssum[NCOL];
    __shared__ unsigned int scnt[NCOL];
    if (threadIdx.x < NCOL) {
        ssum[threadIdx.x] = 0.0f;
        scnt[threadIdx.x] = 0u;
    }
    __syncthreads();

    const int tid    = blockIdx.x * NT + threadIdx.x;
    const int stride = NB * NT;                // multiple of 32
    const int lane   = threadIdx.x & 31;

    Acc a;
    int p = tid;
    for (; p + 3 * stride < n4; p += 4 * stride) {
        process(in4, out4, p,              lane, a);
        process(in4, out4, p + stride,     lane, a);
        process(in4, out4, p + 2 * stride, lane, a);
        process(in4, out4, p + 3 * stride, lane, a);
    }
    for (; p < n4; p += stride) {              // warp-uniform (n4 % 32 == 0)
        process(in4, out4, p, lane, a);
    }

    // Warp tree-reduce across lanes of the same residue class (lane % 4).
    #pragma unroll
    for (int off = 16; off >= 4; off >>= 1) {
        a.s0 += __shfl_down_sync(0xffffffffu, a.s0, off);
        a.s1 += __shfl_down_sync(0xffffffffu, a.s1, off);
        a.s2 += __shfl_down_sync(0xffffffffu, a.s2, off);
        a.s3 += __shfl_down_sync(0xffffffffu, a.s3, off);
        a.c0 += __shfl_down_sync(0xffffffffu, a.c0, off);
        a.c1 += __shfl_down_sync(0xffffffffu, a.c1, off);
        a.c2 += __shfl_down_sync(0xffffffffu, a.c2, off);
        a.c3 += __shfl_down_sync(0xffffffffu, a.c3, off);
    }

    if (lane < 4) {
        const int base = lane * 4;             // column group of this residue class
        atomicAdd(&ssum[base + 0], a.s0);
        atomicAdd(&ssum[base + 1], a.s1);
        atomicAdd(&ssum[base + 2], a.s2);
        atomicAdd(&ssum[base + 3], a.s3);
        atomicAdd(&scnt[base + 0], a.c0);
        atomicAdd(&scnt[base + 1], a.c1);
        atomicAdd(&scnt[base + 2], a.c2);
        atomicAdd(&scnt[base + 3], a.c3);
    }
    __syncthreads();

    if (threadIdx.x < NCOL) {
        atomicAdd(&g_sum[threadIdx.x], ssum[threadIdx.x]);
        atomicAdd(&g_cnt[threadIdx.x], scnt[threadIdx.x]);
    }
}

// ---------------------------------------------------------------------------
// 3) Sparse fix: decode the NaN bitmask, store mean[col] at each NaN slot.
//    ~1.6M scattered 4B stores (5% density) instead of a full 128MB rewrite.
// ---------------------------------------------------------------------------
__global__ void __launch_bounds__(NT) k_fix(float* __restrict__ out, int n_grp) {
    __shared__ float smean[NCOL];
    if (threadIdx.x < NCOL) {
        smean[threadIdx.x] = g_sum[threadIdx.x] /
                             fmaxf((float)g_cnt[threadIdx.x], 1.0f);
    }
    __syncthreads();

    const int tid    = blockIdx.x * NT + threadIdx.x;
    const int stride = NB2 * NT;

    for (int g = tid; g < n_grp; g += stride) {
        uint4 m = *reinterpret_cast<const uint4*>(&g_mask[4 * g]);
        const int base = g << 7;               // 128 * g
        unsigned w;
        w = m.x; while (w) { int b = __ffs(w) - 1; w &= w - 1;
                             out[base + 4*b + 0] = smean[(4*b + 0) & 15]; }
        w = m.y; while (w) { int b = __ffs(w) - 1; w &= w - 1;
                             out[base + 4*b + 1] = smean[(4*b + 1) & 15]; }
        w = m.z; while (w) { int b = __ffs(w) - 1; w &= w - 1;
                             out[base + 4*b + 2] = smean[(4*b + 2) & 15]; }
        w = m.w; while (w) { int b = __ffs(w) - 1; w &= w - 1;
                             out[base + 4*b + 3] = smean[(4*b + 3) & 15]; }
    }
}

// ---------------------------------------------------------------------------
extern "C" void kernel_launch(void* const* d_in, const int* in_sizes, int n_in,
                              void* d_out, int out_size) {
    const float4* in4  = (const float4*)d_in[0];
    float4*       out4 = (float4*)d_out;
    const int n4 = in_sizes[0] / 4;    // 32M floats -> 8M float4

    k_init<<<1, 32>>>();
    k_reduce_copy<<<NB, NT>>>(in4, out4, n4);
    k_fix<<<NB2, NT>>>((float*)d_out, n4 / 32);
}